// round 6
// baseline (speedup 1.0000x reference)
#include <cuda_runtime.h>
#include <cuda_bf16.h>

// ---------------------------------------------------------------------------
// HierarchicalRefinementQuantizer: B=4096, H=3, K=32768, D=128
//   per head: c = argmax_k -(||r||^2 + ||W_k||^2 - 2 r.W_k);  r -= W_c;  q += W_c
// Strategy: 3-term bf16 split GEMM (K=384) on tensor cores for the SEARCH,
// fused chunk-max epilogue, then a rescore of candidate chunks that EMULATES
// the reference's fp32 rounding: s = -( fl(fl(A)+fl(Bk)) - fl(2*dot) ),
// with A, Bk, dot computed in fp64. The reference's decisive rounding happens
// at ulp(||r||^2~128)=1.5e-5; emulating it (rather than computing exactly)
// reproduces its argmax decisions.
// ---------------------------------------------------------------------------

#define B_N 4096
#define D_N 128
#define H_N 3
#define K_N 32768
#define KK  384          // split-K: [hi|hi|lo] x [hi|lo|hi]
#define MT  128          // M tile
#define NT  128          // N tile
#define KC  64           // k-chunk for double buffering
#define NCHUNKS (K_N / NT)   // 256
#define MTILES  (B_N / MT)   // 32
#define SROW 72              // padded smem row stride (bf16 elems) = 144B
#define GEMM_SMEM (4 * MT * SROW * 2)   // 2 bufs * (A+B) = 73728 bytes
#define RESCORE_DELTA 1e-3f

// ------------------------- device scratch (no allocs) ----------------------
__device__ __align__(128) __nv_bfloat16 g_Bbig[H_N][K_N][KK];   // 75.5 MB
__device__ __align__(128) __nv_bfloat16 g_Abig[B_N][KK];        // 3.1 MB
__device__ float  g_wnorm[H_N][K_N];     // 0.5*||W||^2 (fp32, GEMM bias)
__device__ double g_wnormd[H_N][K_N];    // ||W||^2 (fp64, rescore)
__device__ float g_resid[B_N][D_N];
__device__ float g_quant[B_N][D_N];
__device__ float g_pval[B_N][NCHUNKS];

// ------------------------- helpers -----------------------------------------
__device__ __forceinline__ void cp16(void* smem_dst, const void* gsrc) {
    unsigned s = (unsigned)__cvta_generic_to_shared(smem_dst);
    asm volatile("cp.async.cg.shared.global [%0], [%1], 16;\n" :: "r"(s), "l"(gsrc));
}

__device__ __forceinline__ void mma16816(float* d, const unsigned* a, const unsigned* b) {
    asm volatile(
        "mma.sync.aligned.m16n8k16.row.col.f32.bf16.bf16.f32 "
        "{%0,%1,%2,%3}, {%4,%5,%6,%7}, {%8,%9}, {%0,%1,%2,%3};\n"
        : "+f"(d[0]), "+f"(d[1]), "+f"(d[2]), "+f"(d[3])
        : "r"(a[0]), "r"(a[1]), "r"(a[2]), "r"(a[3]), "r"(b[0]), "r"(b[1]));
}

// ------------------------- prep: split emb + norms --------------------------
// one warp per (h, k) codebook row
__global__ void hrq_prep_b(const float* __restrict__ emb) {
    int wg = (blockIdx.x * blockDim.x + threadIdx.x) >> 5;
    int lane = threadIdx.x & 31;
    if (wg >= H_N * K_N) return;
    int h = wg / K_N;
    int k = wg % K_N;
    const float* w = emb + ((size_t)h * K_N + k) * D_N;
    double ssum = 0.0;
#pragma unroll
    for (int j = 0; j < 4; j++) {
        int d = lane + 32 * j;
        float x = w[d];
        __nv_bfloat16 hi = __float2bfloat16_rn(x);
        __nv_bfloat16 lo = __float2bfloat16_rn(x - __bfloat162float(hi));
        g_Bbig[h][k][d]       = hi;
        g_Bbig[h][k][128 + d] = lo;
        g_Bbig[h][k][256 + d] = hi;
        ssum += (double)x * (double)x;
    }
#pragma unroll
    for (int off = 16; off; off >>= 1)
        ssum += __shfl_xor_sync(0xffffffffu, ssum, off);
    if (lane == 0) {
        g_wnorm[h][k]  = 0.5f * (float)ssum;
        g_wnormd[h][k] = ssum;
    }
}

// ------------------------- init: residual + A split + loss ------------------
__global__ void hrq_init(const float* __restrict__ inputs, float* __restrict__ out,
                         long long off_loss) {
    int idx = blockIdx.x * blockDim.x + threadIdx.x;
    if (idx >= B_N * D_N) return;
    int row = idx / D_N, d = idx % D_N;
    float x = inputs[idx];
    g_resid[row][d] = x;
    g_quant[row][d] = 0.f;
    __nv_bfloat16 hi = __float2bfloat16_rn(x);
    __nv_bfloat16 lo = __float2bfloat16_rn(x - __bfloat162float(hi));
    g_Abig[row][d]       = hi;
    g_Abig[row][128 + d] = hi;
    g_Abig[row][256 + d] = lo;
    if (off_loss >= 0 && d == 0) out[off_loss + row] = 0.f;
}

// ------------------------- GEMM + fused chunk-max ---------------------------
extern __shared__ char hrq_smem[];

__global__ __launch_bounds__(256, 2) void hrq_gemm_argmax(int h) {
    const int n0 = blockIdx.x * NT;
    const int m0 = blockIdx.y * MT;
    __nv_bfloat16* As = (__nv_bfloat16*)hrq_smem;        // [2][MT][SROW]
    __nv_bfloat16* Bs = As + 2 * MT * SROW;              // [2][NT][SROW]

    const int tid  = threadIdx.x;
    const int lrow = tid >> 1;
    const int lseg = (tid & 1) * 32;

    auto issue = [&](int c) {
        int buf = c & 1;
        int k0 = c * KC;
        const __nv_bfloat16* ga = &g_Abig[m0 + lrow][k0 + lseg];
        __nv_bfloat16* sa = As + buf * MT * SROW + lrow * SROW + lseg;
#pragma unroll
        for (int j = 0; j < 4; j++) cp16(sa + j * 8, ga + j * 8);
        const __nv_bfloat16* gb = &g_Bbig[h][n0 + lrow][k0 + lseg];
        __nv_bfloat16* sb = Bs + buf * NT * SROW + lrow * SROW + lseg;
#pragma unroll
        for (int j = 0; j < 4; j++) cp16(sb + j * 8, gb + j * 8);
        asm volatile("cp.async.commit_group;\n");
    };

    const int w  = tid >> 5, lane = tid & 31;
    const int wm = w & 3,  wn = w >> 2;       // 4x2 warp grid, warp tile 32x64
    const int g  = lane >> 2, l = lane & 3;

    float acc[2][8][4];
#pragma unroll
    for (int a = 0; a < 2; a++)
#pragma unroll
        for (int b = 0; b < 8; b++)
#pragma unroll
            for (int c = 0; c < 4; c++) acc[a][b][c] = 0.f;

    issue(0);
#pragma unroll
    for (int c = 0; c < KK / KC; c++) {       // 6 chunks
        if (c < KK / KC - 1) {
            issue(c + 1);
            asm volatile("cp.async.wait_group 1;\n");
        } else {
            asm volatile("cp.async.wait_group 0;\n");
        }
        __syncthreads();
        const int buf = c & 1;
        const __nv_bfloat16* Ab = As + buf * MT * SROW;
        const __nv_bfloat16* Bb = Bs + buf * NT * SROW;
#pragma unroll
        for (int ks = 0; ks < KC; ks += 16) {
            unsigned afr[2][4];
#pragma unroll
            for (int mb = 0; mb < 2; mb++) {
                const int R = wm * 32 + mb * 16;
                afr[mb][0] = *(const unsigned*)(Ab + (R + g) * SROW + ks + 2 * l);
                afr[mb][1] = *(const unsigned*)(Ab + (R + g + 8) * SROW + ks + 2 * l);
                afr[mb][2] = *(const unsigned*)(Ab + (R + g) * SROW + ks + 2 * l + 8);
                afr[mb][3] = *(const unsigned*)(Ab + (R + g + 8) * SROW + ks + 2 * l + 8);
            }
#pragma unroll
            for (int nb = 0; nb < 8; nb++) {
                unsigned bfr[2];
                const int C = wn * 64 + nb * 8 + g;
                bfr[0] = *(const unsigned*)(Bb + C * SROW + ks + 2 * l);
                bfr[1] = *(const unsigned*)(Bb + C * SROW + ks + 2 * l + 8);
                mma16816(acc[0][nb], afr[0], bfr);
                mma16816(acc[1][nb], afr[1], bfr);
            }
        }
        __syncthreads();
    }

    // ---- epilogue: bias by -0.5||W||^2, chunk-max (values only) ----
    float bias[8][2];
#pragma unroll
    for (int nb = 0; nb < 8; nb++)
#pragma unroll
        for (int j = 0; j < 2; j++)
            bias[nb][j] = g_wnorm[h][n0 + wn * 64 + nb * 8 + 2 * l + j];

    float* sval = (float*)hrq_smem;              // [128][2] (smem reuse, post-sync)

#pragma unroll
    for (int mb = 0; mb < 2; mb++) {
#pragma unroll
        for (int half = 0; half < 2; half++) {
            float bv = -3.4e38f;
#pragma unroll
            for (int nb = 0; nb < 8; nb++) {
#pragma unroll
                for (int j = 0; j < 2; j++) {
                    float v = acc[mb][nb][half * 2 + j] - bias[nb][j];
                    bv = fmaxf(bv, v);
                }
            }
#pragma unroll
            for (int off = 1; off <= 2; off <<= 1)
                bv = fmaxf(bv, __shfl_xor_sync(0xffffffffu, bv, off));
            if (l == 0) {
                int rloc = wm * 32 + mb * 16 + half * 8 + g;
                sval[rloc * 2 + wn] = bv;
            }
        }
    }
    __syncthreads();
    if (tid < MT) {
        float v0 = fmaxf(sval[tid * 2 + 0], sval[tid * 2 + 1]);
        g_pval[m0 + tid][blockIdx.x] = v0;
    }
}

// ---- reduce: fp32-reference-emulating rescore + residual update ------------
// One warp per row. Find max chunk partial; rescan every chunk within
// RESCORE_DELTA of it, scoring EXACTLY the way the reference's fp32 pipeline
// rounds: s = -( fl( fl(A) + fl(Bk) ) - fl(2*dot) ), A/Bk/dot from fp64.
// Ties (equal fp32 score) break to the LOWEST index (jnp.argmax semantics).
__global__ void hrq_reduce_update(const float* __restrict__ emb,
                                  float* __restrict__ out,
                                  int h, long long off_q, long long off_c) {
    int row  = (blockIdx.x * blockDim.x + threadIdx.x) >> 5;
    int lane = threadIdx.x & 31;
    if (row >= B_N) return;

    // pass 1: max chunk partial
    float bv = -3.4e38f;
#pragma unroll
    for (int j = 0; j < NCHUNKS / 32; j++)
        bv = fmaxf(bv, g_pval[row][lane + 32 * j]);
#pragma unroll
    for (int off = 16; off; off >>= 1)
        bv = fmaxf(bv, __shfl_xor_sync(0xffffffffu, bv, off));
    const float thresh = bv - RESCORE_DELTA;

    // residual in registers (lane-distributed) + A = ||r||^2 (fp64 -> fp32)
    float rreg[4];
    double rrd = 0.0;
#pragma unroll
    for (int j = 0; j < 4; j++) {
        rreg[j] = g_resid[row][lane + 32 * j];
        rrd = fma((double)rreg[j], (double)rreg[j], rrd);
    }
#pragma unroll
    for (int off = 16; off; off >>= 1)
        rrd += __shfl_xor_sync(0xffffffffu, rrd, off);
    const float rr_f = (float)rrd;   // fl(A)

    // pass 2: candidate rescan with reference-emulated fp32 scoring
    float bestsc = -3.4e38f;
    int   besti  = 0x7fffffff;
    for (int ch = 0; ch < NCHUNKS; ch++) {
        if (g_pval[row][ch] < thresh) continue;   // uniform across warp
#pragma unroll
        for (int cc = 0; cc < 4; cc++) {
            int code = ch * NT + cc * 32 + lane;
            const float* wrow = emb + ((size_t)h * K_N + code) * D_N;
            double dot = 0.0;
#pragma unroll
            for (int j = 0; j < 4; j++) {
#pragma unroll
                for (int t = 0; t < 32; t++) {
                    float rv = __shfl_sync(0xffffffffu, rreg[j], t);
                    dot = fma((double)rv, (double)__ldg(wrow + 32 * j + t), dot);
                }
            }
            // Reference fp32 emulation:
            //   X  = fl(A + Bk)           (rounded at ulp(~128) = 1.5e-5)
            //   s  = -fl(X - fl(2*dot))
            float wn_f = (float)g_wnormd[h][code];
            float X    = rr_f + wn_f;
            float m2   = (float)(2.0 * dot);
            float sc   = -(X - m2);
            if (sc > bestsc || (sc == bestsc && code < besti)) { bestsc = sc; besti = code; }
        }
    }
#pragma unroll
    for (int off = 16; off; off >>= 1) {
        float ov = __shfl_xor_sync(0xffffffffu, bestsc, off);
        int   oi = __shfl_xor_sync(0xffffffffu, besti, off);
        if (ov > bestsc || (ov == bestsc && oi < besti)) { bestsc = ov; besti = oi; }
    }
    int c = __shfl_sync(0xffffffffu, besti, 0);

    // residual / quantized update with exact fp32 rows (reference order)
    const float* wrow = emb + ((size_t)h * K_N + c) * D_N;
#pragma unroll
    for (int j = 0; j < 4; j++) {
        int d = lane + 32 * j;
        float wv = wrow[d];
        float r  = g_resid[row][d] - wv;
        float q  = g_quant[row][d] + wv;
        g_resid[row][d] = r;
        g_quant[row][d] = q;
        if (h < H_N - 1) {
            __nv_bfloat16 hi = __float2bfloat16_rn(r);
            __nv_bfloat16 lo = __float2bfloat16_rn(r - __bfloat162float(hi));
            g_Abig[row][d]       = hi;
            g_Abig[row][128 + d] = hi;
            g_Abig[row][256 + d] = lo;
        } else {
            out[off_q + (long long)row * D_N + d] = q;
        }
    }
    if (off_c >= 0 && lane == 0)
        out[off_c + (long long)row * H_N + h] = (float)c;
}

// ------------------------- launch ------------------------------------------
extern "C" void kernel_launch(void* const* d_in, const int* in_sizes, int n_in,
                              void* d_out, int out_size) {
    const float* inputs = (const float*)d_in[0];
    const float* emb    = (const float*)d_in[1];
    if (n_in >= 2 && in_sizes[0] > in_sizes[1]) {
        inputs = (const float*)d_in[1];
        emb    = (const float*)d_in[0];
    }
    float* out = (float*)d_out;

    // Output layout: (loss[B], quantized[B*D], codes[B*H]) flattened, float32.
    long long off_l = -1, off_q = 0, off_c = -1;
    if (out_size == B_N + B_N * D_N + B_N * H_N) {
        off_l = 0; off_q = B_N; off_c = (long long)B_N + (long long)B_N * D_N;
    } else if (out_size == B_N * D_N + B_N * H_N) {
        off_q = 0; off_c = (long long)B_N * D_N;
    } // else: quantized only at offset 0

    cudaFuncSetAttribute(hrq_gemm_argmax,
                         cudaFuncAttributeMaxDynamicSharedMemorySize, GEMM_SMEM);

    // 1. split codebooks + norms (3*32768 rows, warp per row)
    hrq_prep_b<<<(H_N * K_N) / 8, 256>>>(emb);
    // 2. init residual / A split / loss
    hrq_init<<<(B_N * D_N + 255) / 256, 256>>>(inputs, out, off_l);
    // 3. three sequential heads: search (tensor core) + emulated rescore/update
    for (int h = 0; h < H_N; h++) {
        hrq_gemm_argmax<<<dim3(NCHUNKS, MTILES), 256, GEMM_SMEM>>>(h);
        hrq_reduce_update<<<B_N / 8, 256>>>(emb, out, h, off_q, off_c);
    }
}

// round 9
// speedup vs baseline: 2.0774x; 2.0774x over previous
#include <cuda_runtime.h>
#include <cuda_bf16.h>

// ---------------------------------------------------------------------------
// HierarchicalRefinementQuantizer: B=4096, H=3, K=32768, D=128
//   per head: c = argmax_k -(||r||^2 + ||W_k||^2 - 2 r.W_k);  r -= W_c;  q += W_c
// Strategy: plain bf16 GEMM (K=128) on tensor cores localizes the winner's
// 128-code chunk (fused chunk-max epilogue); a throughput-oriented rescore
// (block-per-row, thread-per-code, fp64 dot with 4-way ILP) then EMULATES the
// reference's fp32 rounding: s = -( fl(fl(A)+fl(Bk)) - fl(2*dot) ).
// Window delta is >25 sigma of worst-case bf16 GEMM noise -> winner chunk is
// always in the candidate set; final codes bit-match the reference.
// ---------------------------------------------------------------------------

#define B_N 4096
#define D_N 128
#define H_N 3
#define K_N 32768
#define KK  128          // GEMM K (plain bf16, no split)
#define MT  128          // M tile
#define NT  128          // N tile
#define KC  64           // k-chunk for double buffering
#define NCHUNKS (K_N / NT)   // 256
#define MTILES  (B_N / MT)   // 32
#define SROW 72              // padded smem row stride (bf16 elems) = 144B
#define GEMM_SMEM (4 * MT * SROW * 2)   // 2 bufs * (A+B) = 73728 bytes

// ------------------------- device scratch (no allocs) ----------------------
__device__ __align__(128) __nv_bfloat16 g_Bbig[H_N][K_N][KK];   // 25.2 MB
__device__ __align__(128) __nv_bfloat16 g_Abig[B_N][KK];        // 1.0 MB
__device__ float  g_wnorm[H_N][K_N];     // 0.5*||W||^2 (fp32, GEMM bias)
__device__ double g_wnormd[H_N][K_N];    // ||W||^2 (fp64, rescore)
__device__ float g_resid[B_N][D_N];
__device__ float g_quant[B_N][D_N];
__device__ float g_pval[B_N][NCHUNKS];

// ------------------------- helpers -----------------------------------------
__device__ __forceinline__ void cp16(void* smem_dst, const void* gsrc) {
    unsigned s = (unsigned)__cvta_generic_to_shared(smem_dst);
    asm volatile("cp.async.cg.shared.global [%0], [%1], 16;\n" :: "r"(s), "l"(gsrc));
}

__device__ __forceinline__ void mma16816(float* d, const unsigned* a, const unsigned* b) {
    asm volatile(
        "mma.sync.aligned.m16n8k16.row.col.f32.bf16.bf16.f32 "
        "{%0,%1,%2,%3}, {%4,%5,%6,%7}, {%8,%9}, {%0,%1,%2,%3};\n"
        : "+f"(d[0]), "+f"(d[1]), "+f"(d[2]), "+f"(d[3])
        : "r"(a[0]), "r"(a[1]), "r"(a[2]), "r"(a[3]), "r"(b[0]), "r"(b[1]));
}

// ------------------------- prep: bf16 emb + norms ---------------------------
// one warp per (h, k) codebook row
__global__ void hrq_prep_b(const float* __restrict__ emb) {
    int wg = (blockIdx.x * blockDim.x + threadIdx.x) >> 5;
    int lane = threadIdx.x & 31;
    if (wg >= H_N * K_N) return;
    int h = wg / K_N;
    int k = wg % K_N;
    const float* w = emb + ((size_t)h * K_N + k) * D_N;
    double ssum = 0.0;
#pragma unroll
    for (int j = 0; j < 4; j++) {
        int d = lane + 32 * j;
        float x = w[d];
        g_Bbig[h][k][d] = __float2bfloat16_rn(x);
        ssum += (double)x * (double)x;
    }
#pragma unroll
    for (int off = 16; off; off >>= 1)
        ssum += __shfl_xor_sync(0xffffffffu, ssum, off);
    if (lane == 0) {
        g_wnorm[h][k]  = 0.5f * (float)ssum;
        g_wnormd[h][k] = ssum;
    }
}

// ------------------------- init: residual + A + loss ------------------------
__global__ void hrq_init(const float* __restrict__ inputs, float* __restrict__ out,
                         long long off_loss) {
    int idx = blockIdx.x * blockDim.x + threadIdx.x;
    if (idx >= B_N * D_N) return;
    int row = idx / D_N, d = idx % D_N;
    float x = inputs[idx];
    g_resid[row][d] = x;
    g_quant[row][d] = 0.f;
    g_Abig[row][d]  = __float2bfloat16_rn(x);
    if (off_loss >= 0 && d == 0) out[off_loss + row] = 0.f;
}

// ------------------------- GEMM + fused chunk-max ---------------------------
extern __shared__ char hrq_smem[];

__global__ __launch_bounds__(256, 2) void hrq_gemm_argmax(int h) {
    const int n0 = blockIdx.x * NT;
    const int m0 = blockIdx.y * MT;
    __nv_bfloat16* As = (__nv_bfloat16*)hrq_smem;        // [2][MT][SROW]
    __nv_bfloat16* Bs = As + 2 * MT * SROW;              // [2][NT][SROW]

    const int tid  = threadIdx.x;
    const int lrow = tid >> 1;
    const int lseg = (tid & 1) * 32;

    auto issue = [&](int c) {
        int buf = c & 1;
        int k0 = c * KC;
        const __nv_bfloat16* ga = &g_Abig[m0 + lrow][k0 + lseg];
        __nv_bfloat16* sa = As + buf * MT * SROW + lrow * SROW + lseg;
#pragma unroll
        for (int j = 0; j < 4; j++) cp16(sa + j * 8, ga + j * 8);
        const __nv_bfloat16* gb = &g_Bbig[h][n0 + lrow][k0 + lseg];
        __nv_bfloat16* sb = Bs + buf * NT * SROW + lrow * SROW + lseg;
#pragma unroll
        for (int j = 0; j < 4; j++) cp16(sb + j * 8, gb + j * 8);
        asm volatile("cp.async.commit_group;\n");
    };

    const int w  = tid >> 5, lane = tid & 31;
    const int wm = w & 3,  wn = w >> 2;       // 4x2 warp grid, warp tile 32x64
    const int g  = lane >> 2, l = lane & 3;

    float acc[2][8][4];
#pragma unroll
    for (int a = 0; a < 2; a++)
#pragma unroll
        for (int b = 0; b < 8; b++)
#pragma unroll
            for (int c = 0; c < 4; c++) acc[a][b][c] = 0.f;

    issue(0);
#pragma unroll
    for (int c = 0; c < KK / KC; c++) {       // 2 chunks
        if (c < KK / KC - 1) {
            issue(c + 1);
            asm volatile("cp.async.wait_group 1;\n");
        } else {
            asm volatile("cp.async.wait_group 0;\n");
        }
        __syncthreads();
        const int buf = c & 1;
        const __nv_bfloat16* Ab = As + buf * MT * SROW;
        const __nv_bfloat16* Bb = Bs + buf * NT * SROW;
#pragma unroll
        for (int ks = 0; ks < KC; ks += 16) {
            unsigned afr[2][4];
#pragma unroll
            for (int mb = 0; mb < 2; mb++) {
                const int R = wm * 32 + mb * 16;
                afr[mb][0] = *(const unsigned*)(Ab + (R + g) * SROW + ks + 2 * l);
                afr[mb][1] = *(const unsigned*)(Ab + (R + g + 8) * SROW + ks + 2 * l);
                afr[mb][2] = *(const unsigned*)(Ab + (R + g) * SROW + ks + 2 * l + 8);
                afr[mb][3] = *(const unsigned*)(Ab + (R + g + 8) * SROW + ks + 2 * l + 8);
            }
#pragma unroll
            for (int nb = 0; nb < 8; nb++) {
                unsigned bfr[2];
                const int C = wn * 64 + nb * 8 + g;
                bfr[0] = *(const unsigned*)(Bb + C * SROW + ks + 2 * l);
                bfr[1] = *(const unsigned*)(Bb + C * SROW + ks + 2 * l + 8);
                mma16816(acc[0][nb], afr[0], bfr);
                mma16816(acc[1][nb], afr[1], bfr);
            }
        }
        __syncthreads();
    }

    // ---- epilogue: bias by -0.5||W||^2, chunk-max (values only) ----
    float bias[8][2];
#pragma unroll
    for (int nb = 0; nb < 8; nb++)
#pragma unroll
        for (int j = 0; j < 2; j++)
            bias[nb][j] = g_wnorm[h][n0 + wn * 64 + nb * 8 + 2 * l + j];

    float* sval = (float*)hrq_smem;              // [128][2] (smem reuse, post-sync)

#pragma unroll
    for (int mb = 0; mb < 2; mb++) {
#pragma unroll
        for (int half = 0; half < 2; half++) {
            float bv = -3.4e38f;
#pragma unroll
            for (int nb = 0; nb < 8; nb++) {
#pragma unroll
                for (int j = 0; j < 2; j++) {
                    float v = acc[mb][nb][half * 2 + j] - bias[nb][j];
                    bv = fmaxf(bv, v);
                }
            }
#pragma unroll
            for (int off = 1; off <= 2; off <<= 1)
                bv = fmaxf(bv, __shfl_xor_sync(0xffffffffu, bv, off));
            if (l == 0) {
                int rloc = wm * 32 + mb * 16 + half * 8 + g;
                sval[rloc * 2 + wn] = bv;
            }
        }
    }
    __syncthreads();
    if (tid < MT) {
        float v0 = fmaxf(sval[tid * 2 + 0], sval[tid * 2 + 1]);
        g_pval[m0 + tid][blockIdx.x] = v0;
    }
}

// ---- rescore: block per row, thread per code, fp64 dot, fp32 emulation -----
__global__ __launch_bounds__(128) void hrq_reduce_update(
        const float* __restrict__ emb, float* __restrict__ out,
        int h, long long off_q, long long off_c, float delta) {
    const int row = blockIdx.x;
    const int tid = threadIdx.x;
    const int wid = tid >> 5, lane = tid & 31;

    __shared__ float spval[NCHUNKS];
    __shared__ float sres[D_N];
    __shared__ float swred[4];
    __shared__ double sdred[4];
    __shared__ float ssc[4];
    __shared__ int   sci[4];
    __shared__ float s_bcast;
    __shared__ int   s_code;

    spval[tid]       = g_pval[row][tid];
    spval[tid + 128] = g_pval[row][tid + 128];
    float rv = g_resid[row][tid];
    sres[tid] = rv;

    // ||r||^2 in fp64 (block reduce) -> fl(A)
    double rr = (double)rv * (double)rv;
    // chunk-partial max (block reduce)
    float mv = fmaxf(g_pval[row][tid], g_pval[row][tid + 128]);
#pragma unroll
    for (int off = 16; off; off >>= 1) {
        rr += __shfl_xor_sync(0xffffffffu, rr, off);
        mv  = fmaxf(mv, __shfl_xor_sync(0xffffffffu, mv, off));
    }
    if (lane == 0) { sdred[wid] = rr; swred[wid] = mv; }
    __syncthreads();
    if (tid == 0) {
        double rrt = (sdred[0] + sdred[1]) + (sdred[2] + sdred[3]);
        float  mvt = fmaxf(fmaxf(swred[0], swred[1]), fmaxf(swred[2], swred[3]));
        s_bcast = mvt;
        swred[0] = (float)rrt;      // fl(A)
    }
    __syncthreads();
    const float rr_f   = swred[0];
    const float thresh = s_bcast - delta;

    // candidate chunks: thread tid scores code ch*128 + tid
    float bestsc = -3.4e38f;
    int   besti  = 0x7fffffff;
    for (int ch = 0; ch < NCHUNKS; ch++) {
        if (spval[ch] < thresh) continue;          // uniform across block
        const int code = ch * NT + tid;
        const float4* w4p = (const float4*)(emb + ((size_t)h * K_N + code) * D_N);
        double a0 = 0.0, a1 = 0.0, a2 = 0.0, a3 = 0.0;
#pragma unroll
        for (int i = 0; i < 32; i++) {
            float4 w4 = __ldg(w4p + i);
            a0 = fma((double)sres[4 * i + 0], (double)w4.x, a0);
            a1 = fma((double)sres[4 * i + 1], (double)w4.y, a1);
            a2 = fma((double)sres[4 * i + 2], (double)w4.z, a2);
            a3 = fma((double)sres[4 * i + 3], (double)w4.w, a3);
        }
        double dot = (a0 + a1) + (a2 + a3);
        // Reference fp32 emulation: s = -( fl(fl(A)+fl(Bk)) - fl(2*dot) )
        float wn_f = (float)g_wnormd[h][code];
        float X    = rr_f + wn_f;
        float m2   = (float)(2.0 * dot);
        float sc   = -(X - m2);
        if (sc > bestsc || (sc == bestsc && code < besti)) { bestsc = sc; besti = code; }
    }
    // block argmax (tie -> lowest index)
#pragma unroll
    for (int off = 16; off; off >>= 1) {
        float ov = __shfl_xor_sync(0xffffffffu, bestsc, off);
        int   oi = __shfl_xor_sync(0xffffffffu, besti, off);
        if (ov > bestsc || (ov == bestsc && oi < besti)) { bestsc = ov; besti = oi; }
    }
    if (lane == 0) { ssc[wid] = bestsc; sci[wid] = besti; }
    __syncthreads();
    if (tid == 0) {
        float bs = ssc[0]; int bi = sci[0];
#pragma unroll
        for (int j = 1; j < 4; j++) {
            if (ssc[j] > bs || (ssc[j] == bs && sci[j] < bi)) { bs = ssc[j]; bi = sci[j]; }
        }
        s_code = bi;
    }
    __syncthreads();
    const int c = s_code;

    // residual / quantized update with exact fp32 rows (reference order)
    {
        float wv = emb[((size_t)h * K_N + c) * D_N + tid];
        float r  = g_resid[row][tid] - wv;
        float q  = g_quant[row][tid] + wv;
        g_resid[row][tid] = r;
        g_quant[row][tid] = q;
        if (h < H_N - 1) {
            g_Abig[row][tid] = __float2bfloat16_rn(r);
        } else {
            out[off_q + (long long)row * D_N + tid] = q;
        }
    }
    if (off_c >= 0 && tid == 0)
        out[off_c + (long long)row * H_N + h] = (float)c;
}

// ------------------------- launch ------------------------------------------
extern "C" void kernel_launch(void* const* d_in, const int* in_sizes, int n_in,
                              void* d_out, int out_size) {
    const float* inputs = (const float*)d_in[0];
    const float* emb    = (const float*)d_in[1];
    if (n_in >= 2 && in_sizes[0] > in_sizes[1]) {
        inputs = (const float*)d_in[1];
        emb    = (const float*)d_in[0];
    }
    float* out = (float*)d_out;

    // Output layout: (loss[B], quantized[B*D], codes[B*H]) flattened, float32.
    long long off_l = -1, off_q = 0, off_c = -1;
    if (out_size == B_N + B_N * D_N + B_N * H_N) {
        off_l = 0; off_q = B_N; off_c = (long long)B_N + (long long)B_N * D_N;
    } else if (out_size == B_N * D_N + B_N * H_N) {
        off_q = 0; off_c = (long long)B_N * D_N;
    } // else: quantized only at offset 0

    cudaFuncSetAttribute(hrq_gemm_argmax,
                         cudaFuncAttributeMaxDynamicSharedMemorySize, GEMM_SMEM);

    // rescan window on the v = dot - 0.5||W||^2 scale (score/2):
    // >25 sigma of bf16 GEMM noise per head, ~1.3 chunks/row expected.
    const float deltas[H_N] = {0.03f, 0.015f, 0.0075f};

    // 1. bf16 codebooks + norms
    hrq_prep_b<<<(H_N * K_N) / 8, 256>>>(emb);
    // 2. init residual / A / loss
    hrq_init<<<(B_N * D_N + 255) / 256, 256>>>(inputs, out, off_l);
    // 3. three sequential heads: tensor-core search + emulated rescore/update
    for (int h = 0; h < H_N; h++) {
        hrq_gemm_argmax<<<dim3(NCHUNKS, MTILES), 256, GEMM_SMEM>>>(h);
        hrq_reduce_update<<<B_N, 128>>>(emb, out, h, off_q, off_c, deltas[h]);
    }
}

// round 11
// speedup vs baseline: 5.5624x; 2.6776x over previous
#include <cuda_runtime.h>
#include <cuda_bf16.h>

// ---------------------------------------------------------------------------
// HierarchicalRefinementQuantizer: B=4096, H=3, K=32768, D=128
//   per head: c = argmax_k -(||r||^2 + ||W_k||^2 - 2 r.W_k);  r -= W_c;  q += W_c
// bf16 tensor-core GEMM localizes the winner's 128-code chunk (chunk-max
// epilogue). A rescore (block/row, thread/code) recomputes candidate scores
// with an fp32 COMPENSATED dot (dot2: TwoProdFMA + TwoSum, 4-way ILP) --
// twice-precision accuracy at full fp32 rate, no fp64 in the hot path --
// then emulates the reference's fp32 rounding:
//   s = -( fl(fl(A)+fl(Bk)) - fl(2*dot) ).
// ---------------------------------------------------------------------------

#define B_N 4096
#define D_N 128
#define H_N 3
#define K_N 32768
#define KK  128          // GEMM K (plain bf16)
#define MT  128          // M tile
#define NT  128          // N tile
#define KC  64           // k-chunk for double buffering
#define NCHUNKS (K_N / NT)   // 256
#define MTILES  (B_N / MT)   // 32
#define SROW 72              // padded smem row stride (bf16 elems) = 144B
#define GEMM_SMEM (4 * MT * SROW * 2)   // 2 bufs * (A+B) = 73728 bytes

// ------------------------- device scratch (no allocs) ----------------------
__device__ __align__(128) __nv_bfloat16 g_Bbig[H_N][K_N][KK];   // 25.2 MB
__device__ __align__(128) __nv_bfloat16 g_Abig[B_N][KK];        // 1.0 MB
__device__ float g_wnorm [H_N][K_N];   // 0.5*||W||^2 (fp32, GEMM bias)
__device__ float g_wnormf[H_N][K_N];   // fl(||W||^2) (fp32, rescore)
__device__ float g_resid[B_N][D_N];
__device__ float g_quant[B_N][D_N];
__device__ float g_pval[B_N][NCHUNKS];

// ------------------------- helpers -----------------------------------------
__device__ __forceinline__ void cp16(void* smem_dst, const void* gsrc) {
    unsigned s = (unsigned)__cvta_generic_to_shared(smem_dst);
    asm volatile("cp.async.cg.shared.global [%0], [%1], 16;\n" :: "r"(s), "l"(gsrc));
}

__device__ __forceinline__ void mma16816(float* d, const unsigned* a, const unsigned* b) {
    asm volatile(
        "mma.sync.aligned.m16n8k16.row.col.f32.bf16.bf16.f32 "
        "{%0,%1,%2,%3}, {%4,%5,%6,%7}, {%8,%9}, {%0,%1,%2,%3};\n"
        : "+f"(d[0]), "+f"(d[1]), "+f"(d[2]), "+f"(d[3])
        : "r"(a[0]), "r"(a[1]), "r"(a[2]), "r"(a[3]), "r"(b[0]), "r"(b[1]));
}

// compensated accumulate: (s,c) += a*b  (TwoProdFMA + TwoSum)
__device__ __forceinline__ void dot2_acc(float a, float b, float& s, float& c) {
    float p = a * b;
    float ep = __fmaf_rn(a, b, -p);
    float t = s + p;
    float z = t - s;
    float es = (s - (t - z)) + (p - z);
    s = t;
    c += ep + es;
}

// ------------------------- prep: bf16 emb + norms ---------------------------
// one warp per (h, k) codebook row
__global__ void hrq_prep_b(const float* __restrict__ emb) {
    int wg = (blockIdx.x * blockDim.x + threadIdx.x) >> 5;
    int lane = threadIdx.x & 31;
    if (wg >= H_N * K_N) return;
    int h = wg / K_N;
    int k = wg % K_N;
    const float* w = emb + ((size_t)h * K_N + k) * D_N;
    double ssum = 0.0;
#pragma unroll
    for (int j = 0; j < 4; j++) {
        int d = lane + 32 * j;
        float x = w[d];
        g_Bbig[h][k][d] = __float2bfloat16_rn(x);
        ssum += (double)x * (double)x;
    }
#pragma unroll
    for (int off = 16; off; off >>= 1)
        ssum += __shfl_xor_sync(0xffffffffu, ssum, off);
    if (lane == 0) {
        g_wnorm [h][k] = 0.5f * (float)ssum;
        g_wnormf[h][k] = (float)ssum;
    }
}

// ------------------------- init: residual + A + loss ------------------------
__global__ void hrq_init(const float* __restrict__ inputs, float* __restrict__ out,
                         long long off_loss) {
    int idx = blockIdx.x * blockDim.x + threadIdx.x;
    if (idx >= B_N * D_N) return;
    int row = idx / D_N, d = idx % D_N;
    float x = inputs[idx];
    g_resid[row][d] = x;
    g_quant[row][d] = 0.f;
    g_Abig[row][d]  = __float2bfloat16_rn(x);
    if (off_loss >= 0 && d == 0) out[off_loss + row] = 0.f;
}

// ------------------------- GEMM + fused chunk-max ---------------------------
extern __shared__ char hrq_smem[];

__global__ __launch_bounds__(256, 2) void hrq_gemm_argmax(int h) {
    const int n0 = blockIdx.x * NT;
    const int m0 = blockIdx.y * MT;
    __nv_bfloat16* As = (__nv_bfloat16*)hrq_smem;        // [2][MT][SROW]
    __nv_bfloat16* Bs = As + 2 * MT * SROW;              // [2][NT][SROW]

    const int tid  = threadIdx.x;
    const int lrow = tid >> 1;
    const int lseg = (tid & 1) * 32;

    auto issue = [&](int c) {
        int buf = c & 1;
        int k0 = c * KC;
        const __nv_bfloat16* ga = &g_Abig[m0 + lrow][k0 + lseg];
        __nv_bfloat16* sa = As + buf * MT * SROW + lrow * SROW + lseg;
#pragma unroll
        for (int j = 0; j < 4; j++) cp16(sa + j * 8, ga + j * 8);
        const __nv_bfloat16* gb = &g_Bbig[h][n0 + lrow][k0 + lseg];
        __nv_bfloat16* sb = Bs + buf * NT * SROW + lrow * SROW + lseg;
#pragma unroll
        for (int j = 0; j < 4; j++) cp16(sb + j * 8, gb + j * 8);
        asm volatile("cp.async.commit_group;\n");
    };

    const int w  = tid >> 5, lane = tid & 31;
    const int wm = w & 3,  wn = w >> 2;       // 4x2 warp grid, warp tile 32x64
    const int g  = lane >> 2, l = lane & 3;

    float acc[2][8][4];
#pragma unroll
    for (int a = 0; a < 2; a++)
#pragma unroll
        for (int b = 0; b < 8; b++)
#pragma unroll
            for (int c = 0; c < 4; c++) acc[a][b][c] = 0.f;

    issue(0);
#pragma unroll
    for (int c = 0; c < KK / KC; c++) {       // 2 chunks
        if (c < KK / KC - 1) {
            issue(c + 1);
            asm volatile("cp.async.wait_group 1;\n");
        } else {
            asm volatile("cp.async.wait_group 0;\n");
        }
        __syncthreads();
        const int buf = c & 1;
        const __nv_bfloat16* Ab = As + buf * MT * SROW;
        const __nv_bfloat16* Bb = Bs + buf * NT * SROW;
#pragma unroll
        for (int ks = 0; ks < KC; ks += 16) {
            unsigned afr[2][4];
#pragma unroll
            for (int mb = 0; mb < 2; mb++) {
                const int R = wm * 32 + mb * 16;
                afr[mb][0] = *(const unsigned*)(Ab + (R + g) * SROW + ks + 2 * l);
                afr[mb][1] = *(const unsigned*)(Ab + (R + g + 8) * SROW + ks + 2 * l);
                afr[mb][2] = *(const unsigned*)(Ab + (R + g) * SROW + ks + 2 * l + 8);
                afr[mb][3] = *(const unsigned*)(Ab + (R + g + 8) * SROW + ks + 2 * l + 8);
            }
#pragma unroll
            for (int nb = 0; nb < 8; nb++) {
                unsigned bfr[2];
                const int C = wn * 64 + nb * 8 + g;
                bfr[0] = *(const unsigned*)(Bb + C * SROW + ks + 2 * l);
                bfr[1] = *(const unsigned*)(Bb + C * SROW + ks + 2 * l + 8);
                mma16816(acc[0][nb], afr[0], bfr);
                mma16816(acc[1][nb], afr[1], bfr);
            }
        }
        __syncthreads();
    }

    // ---- epilogue: bias by -0.5||W||^2, chunk-max (values only) ----
    float bias[8][2];
#pragma unroll
    for (int nb = 0; nb < 8; nb++)
#pragma unroll
        for (int j = 0; j < 2; j++)
            bias[nb][j] = g_wnorm[h][n0 + wn * 64 + nb * 8 + 2 * l + j];

    float* sval = (float*)hrq_smem;              // [128][2] (smem reuse, post-sync)

#pragma unroll
    for (int mb = 0; mb < 2; mb++) {
#pragma unroll
        for (int half = 0; half < 2; half++) {
            float bv = -3.4e38f;
#pragma unroll
            for (int nb = 0; nb < 8; nb++) {
#pragma unroll
                for (int j = 0; j < 2; j++) {
                    float v = acc[mb][nb][half * 2 + j] - bias[nb][j];
                    bv = fmaxf(bv, v);
                }
            }
#pragma unroll
            for (int off = 1; off <= 2; off <<= 1)
                bv = fmaxf(bv, __shfl_xor_sync(0xffffffffu, bv, off));
            if (l == 0) {
                int rloc = wm * 32 + mb * 16 + half * 8 + g;
                sval[rloc * 2 + wn] = bv;
            }
        }
    }
    __syncthreads();
    if (tid < MT) {
        float v0 = fmaxf(sval[tid * 2 + 0], sval[tid * 2 + 1]);
        g_pval[m0 + tid][blockIdx.x] = v0;
    }
}

// ---- rescore: block/row, thread/code, fp32 compensated dot -----------------
__global__ __launch_bounds__(128) void hrq_reduce_update(
        const float* __restrict__ emb, float* __restrict__ out,
        int h, long long off_q, long long off_c, float delta) {
    const int row = blockIdx.x;
    const int tid = threadIdx.x;
    const int wid = tid >> 5, lane = tid & 31;

    __shared__ float sres[D_N];
    __shared__ float swred[4];
    __shared__ double sdred[4];
    __shared__ float ssc[4];
    __shared__ int   sci[4];
    __shared__ float s_bcast;
    __shared__ int   s_code;
    __shared__ int   s_cand[NCHUNKS];
    __shared__ int   s_ncand;

    if (tid == 0) s_ncand = 0;
    float p0 = g_pval[row][tid];
    float p1 = g_pval[row][tid + 128];
    float rv = g_resid[row][tid];
    sres[tid] = rv;

    // fl(A) = fp64 ||r||^2 (tiny: 1 DFMA/thread), and chunk-partial max
    double rr = (double)rv * (double)rv;
    float  mv = fmaxf(p0, p1);
#pragma unroll
    for (int off = 16; off; off >>= 1) {
        rr += __shfl_xor_sync(0xffffffffu, rr, off);
        mv  = fmaxf(mv, __shfl_xor_sync(0xffffffffu, mv, off));
    }
    if (lane == 0) { sdred[wid] = rr; swred[wid] = mv; }
    __syncthreads();
    if (tid == 0) {
        double rrt = (sdred[0] + sdred[1]) + (sdred[2] + sdred[3]);
        float  mvt = fmaxf(fmaxf(swred[0], swred[1]), fmaxf(swred[2], swred[3]));
        s_bcast = mvt;
        swred[0] = (float)rrt;      // fl(A)
    }
    __syncthreads();
    const float rr_f   = swred[0];
    const float thresh = s_bcast - delta;

    // gather candidate chunks (order-independent: selection is (sc, min-idx))
    if (p0 >= thresh) s_cand[atomicAdd(&s_ncand, 1)] = tid;
    if (p1 >= thresh) s_cand[atomicAdd(&s_ncand, 1)] = tid + 128;
    __syncthreads();
    const int ncand = s_ncand;

    float bestsc = -3.4e38f;
    int   besti  = 0x7fffffff;
    for (int ci = 0; ci < ncand; ci++) {
        const int ch   = s_cand[ci];
        const int code = ch * NT + tid;
        const float4* w4p = (const float4*)(emb + ((size_t)h * K_N + code) * D_N);
        // fp32 compensated dot, 4 independent (s,c) accumulators
        float s0 = 0.f, c0 = 0.f, s1 = 0.f, c1 = 0.f;
        float s2 = 0.f, c2 = 0.f, s3 = 0.f, c3 = 0.f;
#pragma unroll
        for (int i = 0; i < 32; i++) {
            float4 w4 = __ldg(w4p + i);
            dot2_acc(sres[4 * i + 0], w4.x, s0, c0);
            dot2_acc(sres[4 * i + 1], w4.y, s1, c1);
            dot2_acc(sres[4 * i + 2], w4.z, s2, c2);
            dot2_acc(sres[4 * i + 3], w4.w, s3, c3);
        }
        // compensated pairwise merge of the 4 (s,c) pairs
        float t, z, e, sm01, cm01, sm23, cm23, sm, cm;
        t = s0 + s1; z = t - s0; e = (s0 - (t - z)) + (s1 - z);
        sm01 = t; cm01 = c0 + c1 + e;
        t = s2 + s3; z = t - s2; e = (s2 - (t - z)) + (s3 - z);
        sm23 = t; cm23 = c2 + c3 + e;
        t = sm01 + sm23; z = t - sm01; e = (sm01 - (t - z)) + (sm23 - z);
        sm = t; cm = cm01 + cm23 + e;
        float dot = sm + cm;                 // fl(dot), twice-precision accurate
        // Reference fp32 emulation: s = -( fl(fl(A)+fl(Bk)) - fl(2*dot) )
        float X  = rr_f + g_wnormf[h][code];
        float m2 = 2.0f * dot;               // *2 exact in fp32
        float sc = -(X - m2);
        if (sc > bestsc || (sc == bestsc && code < besti)) { bestsc = sc; besti = code; }
    }
    // block argmax (tie -> lowest index)
#pragma unroll
    for (int off = 16; off; off >>= 1) {
        float ov = __shfl_xor_sync(0xffffffffu, bestsc, off);
        int   oi = __shfl_xor_sync(0xffffffffu, besti, off);
        if (ov > bestsc || (ov == bestsc && oi < besti)) { bestsc = ov; besti = oi; }
    }
    if (lane == 0) { ssc[wid] = bestsc; sci[wid] = besti; }
    __syncthreads();
    if (tid == 0) {
        float bs = ssc[0]; int bi = sci[0];
#pragma unroll
        for (int j = 1; j < 4; j++) {
            if (ssc[j] > bs || (ssc[j] == bs && sci[j] < bi)) { bs = ssc[j]; bi = sci[j]; }
        }
        s_code = bi;
    }
    __syncthreads();
    const int c = s_code;

    // residual / quantized update with exact fp32 rows (reference order)
    {
        float wv = emb[((size_t)h * K_N + c) * D_N + tid];
        float r  = g_resid[row][tid] - wv;
        float q  = g_quant[row][tid] + wv;
        g_resid[row][tid] = r;
        g_quant[row][tid] = q;
        if (h < H_N - 1) {
            g_Abig[row][tid] = __float2bfloat16_rn(r);
        } else {
            out[off_q + (long long)row * D_N + tid] = q;
        }
    }
    if (off_c >= 0 && tid == 0)
        out[off_c + (long long)row * H_N + h] = (float)c;
}

// ------------------------- launch ------------------------------------------
extern "C" void kernel_launch(void* const* d_in, const int* in_sizes, int n_in,
                              void* d_out, int out_size) {
    const float* inputs = (const float*)d_in[0];
    const float* emb    = (const float*)d_in[1];
    if (n_in >= 2 && in_sizes[0] > in_sizes[1]) {
        inputs = (const float*)d_in[1];
        emb    = (const float*)d_in[0];
    }
    float* out = (float*)d_out;

    // Output layout: (loss[B], quantized[B*D], codes[B*H]) flattened, float32.
    long long off_l = -1, off_q = 0, off_c = -1;
    if (out_size == B_N + B_N * D_N + B_N * H_N) {
        off_l = 0; off_q = B_N; off_c = (long long)B_N + (long long)B_N * D_N;
    } else if (out_size == B_N * D_N + B_N * H_N) {
        off_q = 0; off_c = (long long)B_N * D_N;
    } // else: quantized only at offset 0

    cudaFuncSetAttribute(hrq_gemm_argmax,
                         cudaFuncAttributeMaxDynamicSharedMemorySize, GEMM_SMEM);

    // rescan window on the v = dot - 0.5||W||^2 scale (score/2):
    // >25 sigma of bf16 GEMM noise per head, ~1.3 chunks/row expected.
    const float deltas[H_N] = {0.03f, 0.015f, 0.0075f};

    // 1. bf16 codebooks + norms
    hrq_prep_b<<<(H_N * K_N) / 8, 256>>>(emb);
    // 2. init residual / A / loss
    hrq_init<<<(B_N * D_N + 255) / 256, 256>>>(inputs, out, off_l);
    // 3. three sequential heads: tensor-core search + emulated rescore/update
    for (int h = 0; h < H_N; h++) {
        hrq_gemm_argmax<<<dim3(NCHUNKS, MTILES), 256, GEMM_SMEM>>>(h);
        hrq_reduce_update<<<B_N, 128>>>(emb, out, h, off_q, off_c, deltas[h]);
    }
}

// round 12
// speedup vs baseline: 7.4959x; 1.3476x over previous
#include <cuda_runtime.h>
#include <cuda_bf16.h>

// ---------------------------------------------------------------------------
// HierarchicalRefinementQuantizer: B=4096, H=3, K=32768, D=128
//   per head: c = argmax_k -(||r||^2 + ||W_k||^2 - 2 r.W_k);  r -= W_c;  q += W_c
// bf16 tensor-core GEMM with B-RESIDENT chunk CTAs (B tile loaded once,
// 16 M-tiles swept, A double-buffered) produces per-32-code group maxima.
// Rescore: warp-per-code (coalesced W reads), fp32 compensated dot (TwoProdFMA
// + bfly TwoSum tree), emulating the reference's fp32 rounding:
//   s = -( fl(fl(A)+fl(Bk)) - fl(2*dot) ).
// ---------------------------------------------------------------------------

#define B_N 4096
#define D_N 128
#define H_N 3
#define K_N 32768
#define KK  128          // GEMM K (plain bf16)
#define MT  128          // M tile
#define NT  128          // N tile (chunk width)
#define NCHUNKS (K_N / NT)       // 256
#define NGROUPS (K_N / 32)       // 1024  (32-code groups)
#define MHALF   (B_N / 2)        // 2048
#define MTPC    (MHALF / MT)     // 16 M-tiles per CTA
#define SROW 72                  // padded smem row stride (bf16) = 144B
// smem: B resident [2 kc][128][SROW] + A 2 stages [2][2 kc][128][SROW]
#define GEMM_SMEM ((2 * NT * SROW + 4 * MT * SROW) * 2)   // 110592 bytes

// ------------------------- device scratch (no allocs) ----------------------
__device__ __align__(128) __nv_bfloat16 g_Bbig[H_N][K_N][KK];   // 25.2 MB
__device__ __align__(128) __nv_bfloat16 g_Abig[B_N][KK];        // 1.0 MB
__device__ float g_wnorm [H_N][K_N];   // 0.5*||W||^2 (fp32, GEMM bias)
__device__ float g_wnormf[H_N][K_N];   // fl(||W||^2) (fp32, rescore)
__device__ float g_resid[B_N][D_N];
__device__ float g_quant[B_N][D_N];
__device__ __align__(16) float g_pval[B_N][NGROUPS];            // 16 MB

// ------------------------- helpers -----------------------------------------
__device__ __forceinline__ void cp16(void* smem_dst, const void* gsrc) {
    unsigned s = (unsigned)__cvta_generic_to_shared(smem_dst);
    asm volatile("cp.async.cg.shared.global [%0], [%1], 16;\n" :: "r"(s), "l"(gsrc));
}

__device__ __forceinline__ void mma16816(float* d, const unsigned* a, const unsigned* b) {
    asm volatile(
        "mma.sync.aligned.m16n8k16.row.col.f32.bf16.bf16.f32 "
        "{%0,%1,%2,%3}, {%4,%5,%6,%7}, {%8,%9}, {%0,%1,%2,%3};\n"
        : "+f"(d[0]), "+f"(d[1]), "+f"(d[2]), "+f"(d[3])
        : "r"(a[0]), "r"(a[1]), "r"(a[2]), "r"(a[3]), "r"(b[0]), "r"(b[1]));
}

// compensated accumulate: (s,c) += a*b  (TwoProdFMA + TwoSum)
__device__ __forceinline__ void dot2_acc(float a, float b, float& s, float& c) {
    float p = a * b;
    float ep = __fmaf_rn(a, b, -p);
    float t = s + p;
    float z = t - s;
    float es = (s - (t - z)) + (p - z);
    s = t;
    c += ep + es;
}

// ------------------------- prep: bf16 emb + norms ---------------------------
__global__ void hrq_prep_b(const float* __restrict__ emb) {
    int wg = (blockIdx.x * blockDim.x + threadIdx.x) >> 5;
    int lane = threadIdx.x & 31;
    if (wg >= H_N * K_N) return;
    int h = wg / K_N;
    int k = wg % K_N;
    const float* w = emb + ((size_t)h * K_N + k) * D_N;
    double ssum = 0.0;
#pragma unroll
    for (int j = 0; j < 4; j++) {
        int d = lane + 32 * j;
        float x = w[d];
        g_Bbig[h][k][d] = __float2bfloat16_rn(x);
        ssum += (double)x * (double)x;
    }
#pragma unroll
    for (int off = 16; off; off >>= 1)
        ssum += __shfl_xor_sync(0xffffffffu, ssum, off);
    if (lane == 0) {
        g_wnorm [h][k] = 0.5f * (float)ssum;
        g_wnormf[h][k] = (float)ssum;
    }
}

// ------------------------- init: residual + A + loss ------------------------
__global__ void hrq_init(const float* __restrict__ inputs, float* __restrict__ out,
                         long long off_loss) {
    int idx = blockIdx.x * blockDim.x + threadIdx.x;
    if (idx >= B_N * D_N) return;
    int row = idx / D_N, d = idx % D_N;
    float x = inputs[idx];
    g_resid[row][d] = x;
    g_quant[row][d] = 0.f;
    g_Abig[row][d]  = __float2bfloat16_rn(x);
    if (off_loss >= 0 && d == 0) out[off_loss + row] = 0.f;
}

// ---------------- GEMM: B-resident chunk CTA, 16 M-tiles --------------------
extern __shared__ char hrq_smem[];

__global__ __launch_bounds__(256, 2) void hrq_gemm_argmax(int h) {
    const int n0     = blockIdx.x * NT;       // chunk base code
    const int mhalf0 = blockIdx.y * MHALF;    // M half base row
    __nv_bfloat16* Bs = (__nv_bfloat16*)hrq_smem;     // [2 kc][128][SROW]
    __nv_bfloat16* As = Bs + 2 * NT * SROW;           // [2 st][2 kc][128][SROW]

    __shared__ float sval[MT * 4];            // per-tile group maxima

    const int tid  = threadIdx.x;
    const int lrow = tid >> 1;
    const int lseg = (tid & 1) * 32;

    // ---- load B tile once (both k-chunks), one commit group ----
#pragma unroll
    for (int kc = 0; kc < 2; kc++) {
        const __nv_bfloat16* gb = &g_Bbig[h][n0 + lrow][kc * 64 + lseg];
        __nv_bfloat16* sb = Bs + kc * NT * SROW + lrow * SROW + lseg;
#pragma unroll
        for (int j = 0; j < 4; j++) cp16(sb + j * 8, gb + j * 8);
    }
    asm volatile("cp.async.commit_group;\n");

    auto issueA = [&](int m, int st) {
        const int mbase = mhalf0 + m * MT;
#pragma unroll
        for (int kc = 0; kc < 2; kc++) {
            const __nv_bfloat16* ga = &g_Abig[mbase + lrow][kc * 64 + lseg];
            __nv_bfloat16* sa = As + (st * 2 + kc) * MT * SROW + lrow * SROW + lseg;
#pragma unroll
            for (int j = 0; j < 4; j++) cp16(sa + j * 8, ga + j * 8);
        }
        asm volatile("cp.async.commit_group;\n");
    };

    issueA(0, 0);
    issueA(1, 1);

    const int w  = tid >> 5, lane = tid & 31;
    const int wm = w & 3,  wn = w >> 2;       // 4x2 warp grid, warp tile 32x64
    const int g  = lane >> 2, l = lane & 3;

    // bias: chunk-fixed, hoisted out of the M loop
    float bias[8][2];
#pragma unroll
    for (int nb = 0; nb < 8; nb++)
#pragma unroll
        for (int j = 0; j < 2; j++)
            bias[nb][j] = g_wnorm[h][n0 + wn * 64 + nb * 8 + 2 * l + j];

    asm volatile("cp.async.wait_group 1;\n");   // B + A[0] arrived
    __syncthreads();

    for (int m = 0; m < MTPC; m++) {
        const int st = m & 1;
        float acc[2][8][4];
#pragma unroll
        for (int a = 0; a < 2; a++)
#pragma unroll
            for (int b = 0; b < 8; b++)
#pragma unroll
                for (int c = 0; c < 4; c++) acc[a][b][c] = 0.f;

#pragma unroll
        for (int kc = 0; kc < 2; kc++) {
            const __nv_bfloat16* Ab = As + (st * 2 + kc) * MT * SROW;
            const __nv_bfloat16* Bb = Bs + kc * NT * SROW;
#pragma unroll
            for (int ks = 0; ks < 64; ks += 16) {
                unsigned afr[2][4];
#pragma unroll
                for (int mb = 0; mb < 2; mb++) {
                    const int R = wm * 32 + mb * 16;
                    afr[mb][0] = *(const unsigned*)(Ab + (R + g) * SROW + ks + 2 * l);
                    afr[mb][1] = *(const unsigned*)(Ab + (R + g + 8) * SROW + ks + 2 * l);
                    afr[mb][2] = *(const unsigned*)(Ab + (R + g) * SROW + ks + 2 * l + 8);
                    afr[mb][3] = *(const unsigned*)(Ab + (R + g + 8) * SROW + ks + 2 * l + 8);
                }
#pragma unroll
                for (int nb = 0; nb < 8; nb++) {
                    unsigned bfr[2];
                    const int C = wn * 64 + nb * 8 + g;
                    bfr[0] = *(const unsigned*)(Bb + C * SROW + ks + 2 * l);
                    bfr[1] = *(const unsigned*)(Bb + C * SROW + ks + 2 * l + 8);
                    mma16816(acc[0][nb], afr[0], bfr);
                    mma16816(acc[1][nb], afr[1], bfr);
                }
            }
        }
        __syncthreads();                       // stage st reads complete
        const bool pre = (m + 2 < MTPC);
        if (pre) issueA(m + 2, st);            // refill freed stage

        // ---- epilogue: per-32-code group maxima (bias applied per code) ----
#pragma unroll
        for (int mb = 0; mb < 2; mb++) {
#pragma unroll
            for (int half = 0; half < 2; half++) {
                float gm[2] = {-3.4e38f, -3.4e38f};
#pragma unroll
                for (int nb = 0; nb < 8; nb++) {
#pragma unroll
                    for (int j = 0; j < 2; j++) {
                        float v = acc[mb][nb][half * 2 + j] - bias[nb][j];
                        gm[nb >> 2] = fmaxf(gm[nb >> 2], v);
                    }
                }
#pragma unroll
                for (int off = 1; off <= 2; off <<= 1) {
                    gm[0] = fmaxf(gm[0], __shfl_xor_sync(0xffffffffu, gm[0], off));
                    gm[1] = fmaxf(gm[1], __shfl_xor_sync(0xffffffffu, gm[1], off));
                }
                if (l == 0) {
                    int rloc = wm * 32 + mb * 16 + half * 8 + g;
                    sval[rloc * 4 + wn * 2 + 0] = gm[0];
                    sval[rloc * 4 + wn * 2 + 1] = gm[1];
                }
            }
        }
        if (pre) { asm volatile("cp.async.wait_group 1;\n"); }
        else     { asm volatile("cp.async.wait_group 0;\n"); }
        __syncthreads();                       // sval ready + next A visible
        if (tid < MT) {
            float4 v4 = *(float4*)&sval[tid * 4];
            *(float4*)&g_pval[mhalf0 + m * MT + tid][blockIdx.x * 4] = v4;
        }
    }
}

// ---- rescore: warp-per-code, coalesced W reads, fp32 compensated dot -------
__global__ __launch_bounds__(128) void hrq_reduce_update(
        const float* __restrict__ emb, float* __restrict__ out,
        int h, long long off_q, long long off_c, float delta) {
    const int row = blockIdx.x;
    const int tid = threadIdx.x;
    const int wid = tid >> 5, lane = tid & 31;

    __shared__ float sres[D_N];
    __shared__ float swred[4];
    __shared__ double sdred[4];
    __shared__ float ssc[4];
    __shared__ int   sci[4];
    __shared__ float s_bcast;
    __shared__ int   s_code;
    __shared__ int   s_cand[NGROUPS];
    __shared__ int   s_ncand;

    if (tid == 0) s_ncand = 0;
    float rv = g_resid[row][tid];
    sres[tid] = rv;

    // per-thread 8 group partials (two float4 loads, coalesced)
    float4 pa = __ldg((const float4*)&g_pval[row][tid * 8]);
    float4 pb = __ldg((const float4*)&g_pval[row][tid * 8 + 4]);
    float pv[8] = {pa.x, pa.y, pa.z, pa.w, pb.x, pb.y, pb.z, pb.w};

    // fl(A) = fp64 ||r||^2 (1 DFMA/thread) + group-partial max
    double rr = (double)rv * (double)rv;
    float  mv = pv[0];
#pragma unroll
    for (int j = 1; j < 8; j++) mv = fmaxf(mv, pv[j]);
#pragma unroll
    for (int off = 16; off; off >>= 1) {
        rr += __shfl_xor_sync(0xffffffffu, rr, off);
        mv  = fmaxf(mv, __shfl_xor_sync(0xffffffffu, mv, off));
    }
    if (lane == 0) { sdred[wid] = rr; swred[wid] = mv; }
    __syncthreads();
    if (tid == 0) {
        double rrt = (sdred[0] + sdred[1]) + (sdred[2] + sdred[3]);
        float  mvt = fmaxf(fmaxf(swred[0], swred[1]), fmaxf(swred[2], swred[3]));
        s_bcast = mvt;
        swred[0] = (float)rrt;      // fl(A)
    }
    __syncthreads();
    const float rr_f   = swred[0];
    const float thresh = s_bcast - delta;

    // gather candidate groups (order-independent: selection is (sc, min-idx))
#pragma unroll
    for (int j = 0; j < 8; j++)
        if (pv[j] >= thresh) s_cand[atomicAdd(&s_ncand, 1)] = tid * 8 + j;
    __syncthreads();
    const int ncand = s_ncand;

    // each warp's lanes split the 128 dims: lane owns dims [4*lane, 4*lane+4)
    const float4 rq = *(const float4*)&sres[4 * lane];

    float bestsc = -3.4e38f;
    int   besti  = 0x7fffffff;
    for (int ci = 0; ci < ncand; ci++) {
        const int base = s_cand[ci] * 32 + wid * 8;   // warp's 8 codes
#pragma unroll
        for (int i = 0; i < 8; i++) {
            const int code = base + i;
            float4 w4 = __ldg((const float4*)(emb + ((size_t)h * K_N + code) * D_N) + lane);
            float s = 0.f, c = 0.f;
            dot2_acc(rq.x, w4.x, s, c);
            dot2_acc(rq.y, w4.y, s, c);
            dot2_acc(rq.z, w4.z, s, c);
            dot2_acc(rq.w, w4.w, s, c);
            // bfly TwoSum merge tree: all lanes end with identical (s,c)
#pragma unroll
            for (int off = 16; off; off >>= 1) {
                float so = __shfl_xor_sync(0xffffffffu, s, off);
                float co = __shfl_xor_sync(0xffffffffu, c, off);
                float t = s + so;
                float z = t - s;
                float e = (s - (t - z)) + (so - z);
                s = t;
                c = c + co + e;
            }
            float dot = s + c;                       // fl(dot), twice-precision
            // Reference fp32 emulation: s = -( fl(fl(A)+fl(Bk)) - fl(2*dot) )
            float X  = rr_f + __ldg(&g_wnormf[h][code]);
            float sc = -(X - 2.0f * dot);
            if (sc > bestsc || (sc == bestsc && code < besti)) { bestsc = sc; besti = code; }
        }
    }
    // cross-warp argmax (tie -> lowest index)
    if (lane == 0) { ssc[wid] = bestsc; sci[wid] = besti; }
    __syncthreads();
    if (tid == 0) {
        float bs = ssc[0]; int bi = sci[0];
#pragma unroll
        for (int j = 1; j < 4; j++) {
            if (ssc[j] > bs || (ssc[j] == bs && sci[j] < bi)) { bs = ssc[j]; bi = sci[j]; }
        }
        s_code = bi;
    }
    __syncthreads();
    const int c = s_code;

    // residual / quantized update with exact fp32 rows (reference order)
    {
        float wv = emb[((size_t)h * K_N + c) * D_N + tid];
        float r  = g_resid[row][tid] - wv;
        float q  = g_quant[row][tid] + wv;
        g_resid[row][tid] = r;
        g_quant[row][tid] = q;
        if (h < H_N - 1) {
            g_Abig[row][tid] = __float2bfloat16_rn(r);
        } else {
            out[off_q + (long long)row * D_N + tid] = q;
        }
    }
    if (off_c >= 0 && tid == 0)
        out[off_c + (long long)row * H_N + h] = (float)c;
}

// ------------------------- launch ------------------------------------------
extern "C" void kernel_launch(void* const* d_in, const int* in_sizes, int n_in,
                              void* d_out, int out_size) {
    const float* inputs = (const float*)d_in[0];
    const float* emb    = (const float*)d_in[1];
    if (n_in >= 2 && in_sizes[0] > in_sizes[1]) {
        inputs = (const float*)d_in[1];
        emb    = (const float*)d_in[0];
    }
    float* out = (float*)d_out;

    // Output layout: (loss[B], quantized[B*D], codes[B*H]) flattened, float32.
    long long off_l = -1, off_q = 0, off_c = -1;
    if (out_size == B_N + B_N * D_N + B_N * H_N) {
        off_l = 0; off_q = B_N; off_c = (long long)B_N + (long long)B_N * D_N;
    } else if (out_size == B_N * D_N + B_N * H_N) {
        off_q = 0; off_c = (long long)B_N * D_N;
    } // else: quantized only at offset 0

    cudaFuncSetAttribute(hrq_gemm_argmax,
                         cudaFuncAttributeMaxDynamicSharedMemorySize, GEMM_SMEM);

    // rescan window on the v = dot - 0.5||W||^2 scale (score/2):
    // >25 sigma of bf16 GEMM noise per head.
    const float deltas[H_N] = {0.03f, 0.015f, 0.0075f};

    // 1. bf16 codebooks + norms
    hrq_prep_b<<<(H_N * K_N) / 8, 256>>>(emb);
    // 2. init residual / A / loss
    hrq_init<<<(B_N * D_N + 255) / 256, 256>>>(inputs, out, off_l);
    // 3. three sequential heads: tensor-core search + emulated rescore/update
    for (int h = 0; h < H_N; h++) {
        hrq_gemm_argmax<<<dim3(NCHUNKS, 2), 256, GEMM_SMEM>>>(h);
        hrq_reduce_update<<<B_N, 128>>>(emb, out, h, off_q, off_c, deltas[h]);
    }
}